// round 2
// baseline (speedup 1.0000x reference)
#include <cuda_runtime.h>
#include <cuda_fp16.h>
#include <cstdint>

// ====================== problem constants ======================
#define M_TOTAL 8192
#define N_TOTAL 16384
#define K_TOTAL 4096

#define TM 128
#define TN 256
#define TK 64                    // fp16 elems per K-chunk (128 bytes per row)
#define STAGES 4
#define KITERS (K_TOTAL / TK)    // 64
#define THREADS 512              // 16 warps: 4 (M) x 4 (N), warp tile 32x64

#define A_BYTES (TM * TK * 2)           // 16384
#define W_BYTES (TN * TK * 2)           // 32768
#define STAGE_BYTES (A_BYTES + W_BYTES) // 49152

#define OFF_SCALE (STAGES * STAGE_BYTES)   // 196608
#define OFF_BIAS  (OFF_SCALE + 1024)
#define SMEM_NEED (OFF_BIAS + 1024)
#define SMEM_DYN  (SMEM_NEED + 1024)       // + 1024 alignment slack

// ====================== device scratch (no cudaMalloc allowed) ======================
__device__ __align__(128) __half g_A[(size_t)M_TOTAL * K_TOTAL]; // fp16 activations
__device__ __align__(128) __half g_W[(size_t)N_TOTAL * K_TOTAL]; // fp16 weights (exact ints)

// ====================== PTX helpers (ALL generic-PTX, no 'a' features) ======
__device__ __forceinline__ uint32_t smem_u32(const void* p) {
    uint32_t a;
    asm("{ .reg .u64 t; cvta.to.shared.u64 t, %1; cvt.u32.u64 %0, t; }" : "=r"(a) : "l"(p));
    return a;
}

__device__ __forceinline__ void cp16(uint32_t dst, const void* src) {
    asm volatile("cp.async.cg.shared.global [%0], [%1], 16;" :: "r"(dst), "l"(src));
}
#define CP_COMMIT() asm volatile("cp.async.commit_group;" ::: "memory")
#define CP_WAIT2()  asm volatile("cp.async.wait_group 2;"  ::: "memory")

__device__ __forceinline__ void ldsm4(uint32_t* r, uint32_t addr) {
    asm volatile("ldmatrix.sync.aligned.m8n8.x4.shared.b16 {%0,%1,%2,%3}, [%4];"
                 : "=r"(r[0]), "=r"(r[1]), "=r"(r[2]), "=r"(r[3]) : "r"(addr));
}

__device__ __forceinline__ void mma16816(float* c, const uint32_t* a, uint32_t b0, uint32_t b1) {
    asm volatile(
        "mma.sync.aligned.m16n8k16.row.col.f32.f16.f16.f32 "
        "{%0,%1,%2,%3}, {%4,%5,%6,%7}, {%8,%9}, {%0,%1,%2,%3};"
        : "+f"(c[0]), "+f"(c[1]), "+f"(c[2]), "+f"(c[3])
        : "r"(a[0]), "r"(a[1]), "r"(a[2]), "r"(a[3]), "r"(b0), "r"(b1));
}

// SW128-style XOR swizzle for 128B rows: bits[9:7] (row%8) XOR into bits[6:4]
__device__ __forceinline__ uint32_t swz(uint32_t byte) {
    return byte ^ ((byte >> 3) & 0x70u);
}

// ====================== pre-convert kernels ======================
struct h4 { __half2 a, b; };

__global__ void conv_a_kernel(const float4* __restrict__ in, h4* __restrict__ out, int n4) {
    int i = blockIdx.x * blockDim.x + threadIdx.x;
    if (i < n4) {
        float4 v = in[i];
        h4 o;
        o.a = __floats2half2_rn(v.x, v.y);
        o.b = __floats2half2_rn(v.z, v.w);
        out[i] = o;
    }
}

__global__ void conv_w_kernel(const int4* __restrict__ in, h4* __restrict__ out, int n4) {
    int i = blockIdx.x * blockDim.x + threadIdx.x;
    if (i < n4) {
        int4 w = in[i];
        h4 o;
        o.a = __floats2half2_rn((float)w.x, (float)w.y);  // |w|<=127: exact in fp16
        o.b = __floats2half2_rn((float)w.z, (float)w.w);
        out[i] = o;
    }
}

// ====================== GEMM kernel (HMMA via mma.sync) ======================
__global__ void __launch_bounds__(THREADS, 1) qlinear_gemm(
    const float* __restrict__ scale,
    const float* __restrict__ bias,
    float* __restrict__ out)
{
    extern __shared__ char smem_raw[];
    uint32_t raw = smem_u32(smem_raw);
    uint32_t pad = (1024u - (raw & 1023u)) & 1023u;
    uint32_t sb = raw + pad;                 // 1024-aligned smem base (u32 shared addr)
    char* smbase = smem_raw + pad;

    const int tid = threadIdx.x;
    const int wid = tid >> 5;
    const int lid = tid & 31;
    const int warp_m = wid & 3;              // 4 warps along M (32 rows each)
    const int warp_n = wid >> 2;             // 4 warps along N (64 cols each)

    // ---- tile rasterization: groups of 8 N-tiles, sweep all M-tiles within group ----
    const int MT = M_TOTAL / TM;             // 64
    const int G = 8;
    const int PER = G * MT;                  // 512
    int bid = blockIdx.x;
    int grp = bid / PER;
    int r = bid % PER;
    int nt = grp * G + (r % G);
    int mt = r / G;
    int m0 = mt * TM;
    int n0 = nt * TN;

    // ---- scale/bias -> smem ----
    float* ssm = (float*)(smbase + OFF_SCALE);
    float* bsm = (float*)(smbase + OFF_BIAS);
    if (tid < TN) {
        ssm[tid] = scale[n0 + tid];
        bsm[tid] = bias[n0 + tid];
    }

    // ---- cp.async per-thread source/dest precompute ----
    // A: 1024 16B-chunks/stage, 2 per thread. W: 2048 chunks, 4 per thread.
    int arow0 = tid >> 3;                    // chunk = tid      -> rows 0..63
    int arow1 = (tid + THREADS) >> 3;        // chunk = tid+512  -> rows 64..127
    int ac = tid & 7;
    uint32_t adst0 = arow0 * 128 + swz(ac * 16); // swizzle only touches low 7 bits + row low bits
    uint32_t adst1 = arow1 * 128 + ((ac * 16) ^ ((arow1 & 7) << 4));
    adst0 = arow0 * 128 + ((ac * 16) ^ ((arow0 & 7) << 4));
    const __half* asrc0 = g_A + (size_t)(m0 + arow0) * K_TOTAL + ac * 8;
    const __half* asrc1 = g_A + (size_t)(m0 + arow1) * K_TOTAL + ac * 8;

    int wrow[4];
    uint32_t wdst[4];
    const __half* wsrc[4];
    #pragma unroll
    for (int j = 0; j < 4; ++j) {
        int chunk = tid + j * THREADS;       // 0..2047
        int row = chunk >> 3;                // 0..255
        int c = chunk & 7;
        wrow[j] = row;
        wdst[j] = A_BYTES + row * 128 + ((c * 16) ^ ((row & 7) << 4));
        wsrc[j] = g_W + (size_t)(n0 + row) * K_TOTAL + c * 8;
    }

    // ---- ldmatrix lane address precompute ----
    int lrow = lid & 15;
    int lk16 = (lid >> 4) * 16;              // byte offset of 16B column half
    // A: 2 m-tiles of 16 rows
    uint32_t a_rb[2], a_rx[2];
    #pragma unroll
    for (int mtt = 0; mtt < 2; ++mtt) {
        int rowi = warp_m * 32 + mtt * 16 + lrow;
        a_rb[mtt] = rowi * 128;
        a_rx[mtt] = (rowi & 7) << 4;
    }
    // W: 4 n16-blocks per warp
    uint32_t b_rb[4], b_rx[4];
    #pragma unroll
    for (int nb = 0; nb < 4; ++nb) {
        int rowi = warp_n * 64 + nb * 16 + lrow;
        b_rb[nb] = A_BYTES + rowi * 128;
        b_rx[nb] = (rowi & 7) << 4;
    }

    // ---- prologue: fill 3 stages ----
    #pragma unroll
    for (int s = 0; s < STAGES - 1; ++s) {
        uint32_t st = sb + s * STAGE_BYTES;
        int koff = s * TK;
        cp16(st + adst0, asrc0 + koff);
        cp16(st + adst1, asrc1 + koff);
        #pragma unroll
        for (int j = 0; j < 4; ++j) cp16(st + wdst[j], wsrc[j] + koff);
        CP_COMMIT();
    }

    float acc[2][8][4];
    #pragma unroll
    for (int i = 0; i < 2; ++i)
        #pragma unroll
        for (int j = 0; j < 8; ++j)
            #pragma unroll
            for (int k = 0; k < 4; ++k) acc[i][j][k] = 0.0f;

    // ---- mainloop ----
    for (int it = 0; it < KITERS; ++it) {
        CP_WAIT2();
        __syncthreads();

        // issue loads for stage it+3 (uniform commit keeps group accounting aligned)
        int nit = it + STAGES - 1;
        if (nit < KITERS) {
            uint32_t st = sb + (nit & (STAGES - 1)) * STAGE_BYTES;
            int koff = nit * TK;
            cp16(st + adst0, asrc0 + koff);
            cp16(st + adst1, asrc1 + koff);
            #pragma unroll
            for (int j = 0; j < 4; ++j) cp16(st + wdst[j], wsrc[j] + koff);
        }
        CP_COMMIT();

        // compute on stage it
        uint32_t st = sb + (it & (STAGES - 1)) * STAGE_BYTES;
        #pragma unroll
        for (int ks = 0; ks < 4; ++ks) {
            uint32_t kb = ks * 32 + lk16;
            uint32_t a[2][4], b[4][4];
            #pragma unroll
            for (int mtt = 0; mtt < 2; ++mtt)
                ldsm4(a[mtt], st + a_rb[mtt] + (kb ^ a_rx[mtt]));
            #pragma unroll
            for (int nb = 0; nb < 4; ++nb)
                ldsm4(b[nb], st + b_rb[nb] + (kb ^ b_rx[nb]));
            #pragma unroll
            for (int mtt = 0; mtt < 2; ++mtt) {
                #pragma unroll
                for (int nb = 0; nb < 4; ++nb) {
                    mma16816(acc[mtt][2 * nb],     a[mtt], b[nb][0], b[nb][2]);
                    mma16816(acc[mtt][2 * nb + 1], a[mtt], b[nb][1], b[nb][3]);
                }
            }
        }
    }

    // ---- epilogue: scale * acc + bias, fp32 stores ----
    int qrow = lid >> 2;                       // 0..7
    int qcol = (lid & 3) * 2;                  // 0,2,4,6
    #pragma unroll
    for (int mtt = 0; mtt < 2; ++mtt) {
        int r0 = m0 + warp_m * 32 + mtt * 16 + qrow;
        int r1 = r0 + 8;
        #pragma unroll
        for (int nb8 = 0; nb8 < 8; ++nb8) {
            int nl = warp_n * 64 + nb8 * 8 + qcol;   // local n within tile
            float s0 = ssm[nl], s1 = ssm[nl + 1];
            float b0 = bsm[nl], b1 = bsm[nl + 1];
            float2 v0, v1;
            v0.x = acc[mtt][nb8][0] * s0 + b0;
            v0.y = acc[mtt][nb8][1] * s1 + b1;
            v1.x = acc[mtt][nb8][2] * s0 + b0;
            v1.y = acc[mtt][nb8][3] * s1 + b1;
            *reinterpret_cast<float2*>(out + (size_t)r0 * N_TOTAL + n0 + nl) = v0;
            *reinterpret_cast<float2*>(out + (size_t)r1 * N_TOTAL + n0 + nl) = v1;
        }
    }
}

// ====================== host launch ======================
extern "C" void kernel_launch(void* const* d_in, const int* in_sizes, int n_in,
                              void* d_out, int out_size) {
    const float* inp = (const float*)d_in[0];   // [4,2048,4096] fp32
    const int*   qw  = (const int*)d_in[1];     // [16384,4096] int32
    const float* sw  = (const float*)d_in[2];   // [16384]
    const float* bs  = (const float*)d_in[3];   // [16384]
    float* out = (float*)d_out;

    void *pA = nullptr, *pW = nullptr;
    cudaGetSymbolAddress(&pA, g_A);
    cudaGetSymbolAddress(&pW, g_W);

    // pre-convert: A fp32->fp16, W int32->fp16 (exact)
    {
        int n4 = (M_TOTAL * K_TOTAL) / 4;
        conv_a_kernel<<<n4 / 256, 256>>>((const float4*)inp, (h4*)pA, n4);
    }
    {
        int n4 = (N_TOTAL * K_TOTAL) / 4;
        conv_w_kernel<<<n4 / 256, 256>>>((const int4*)qw, (h4*)pW, n4);
    }

    cudaFuncSetAttribute(qlinear_gemm, cudaFuncAttributeMaxDynamicSharedMemorySize, SMEM_DYN);
    int grid = (M_TOTAL / TM) * (N_TOTAL / TN);  // 64 * 64 = 4096
    qlinear_gemm<<<grid, THREADS, SMEM_DYN>>>(sw, bs, out);
}

// round 3
// speedup vs baseline: 1.1106x; 1.1106x over previous
#include <cuda_runtime.h>
#include <cuda_fp16.h>
#include <cstdint>

// ====================== problem constants ======================
#define M_TOTAL 8192
#define N_TOTAL 16384
#define K_TOTAL 4096

#define TM 128
#define TN 256
#define TK 64                    // fp16 elems per K-chunk (128 bytes per row)
#define STAGES 4
#define KITERS (K_TOTAL / TK)    // 64
#define THREADS 512              // 16 warps: 4 (M) x 4 (N), warp tile 32x64

#define A_BYTES (TM * TK * 2)           // 16384 (one A tile)
#define W_BYTES (TN * TK * 2)           // 32768 (one W tile)
#define STAGE_BYTES (A_BYTES + W_BYTES) // 49152

#define OFF_SCALE (STAGES * STAGE_BYTES)   // 196608
#define OFF_BIAS  (OFF_SCALE + 1024)
#define OFF_BAR   (OFF_BIAS + 1024)        // [full(8B), empty(8B)] x STAGES
#define SMEM_NEED (OFF_BAR + STAGES * 16)
#define SMEM_DYN  (SMEM_NEED + 1024)       // + 1024 alignment slack

// ====================== device scratch (pre-swizzled tiled layouts) ======================
// A: tiles [mt][kit] of TM x 128B (SW128-swizzled rows), 16KB each, contiguous
// W: tiles [nt][kit] of TN x 128B (SW128-swizzled rows), 32KB each, contiguous
__device__ __align__(128) __half g_A[(size_t)M_TOTAL * K_TOTAL];
__device__ __align__(128) __half g_W[(size_t)N_TOTAL * K_TOTAL];

// ====================== PTX helpers (generic PTX only, no 'a' features) ======
__device__ __forceinline__ uint32_t smem_u32(const void* p) {
    uint32_t a;
    asm("{ .reg .u64 t; cvta.to.shared.u64 t, %1; cvt.u32.u64 %0, t; }" : "=r"(a) : "l"(p));
    return a;
}

#define MBAR_INIT(addr, cnt) \
    asm volatile("mbarrier.init.shared.b64 [%0], %1;" :: "r"(addr), "r"(cnt) : "memory")

#define MBAR_EXPECT_TX(addr, bytes) \
    asm volatile("mbarrier.arrive.expect_tx.shared.b64 _, [%0], %1;" :: "r"(addr), "r"(bytes) : "memory")

#define MBAR_ARRIVE(addr) \
    asm volatile("mbarrier.arrive.shared.b64 _, [%0];" :: "r"(addr) : "memory")

__device__ __forceinline__ void mbar_wait(uint32_t mbar, uint32_t parity) {
    asm volatile(
        "{\n\t.reg .pred P;\n\t"
        "WAIT_%=:\n\t"
        "mbarrier.try_wait.parity.acquire.cta.shared::cta.b64 P, [%0], %1, 0x989680;\n\t"
        "@P bra.uni DONE_%=;\n\t"
        "bra.uni WAIT_%=;\n\t"
        "DONE_%=:\n\t}"
        :: "r"(mbar), "r"(parity) : "memory");
}

__device__ __forceinline__ void mbar_wait_relaxed(uint32_t mbar, uint32_t parity) {
    asm volatile(
        "{\n\t.reg .pred P;\n\t"
        "WAIT_%=:\n\t"
        "mbarrier.try_wait.parity.relaxed.cta.shared::cta.b64 P, [%0], %1, 0x989680;\n\t"
        "@P bra.uni DONE_%=;\n\t"
        "bra.uni WAIT_%=;\n\t"
        "DONE_%=:\n\t}"
        :: "r"(mbar), "r"(parity) : "memory");
}

// 1D bulk async copy global->shared with mbarrier completion (baseline sm_90 PTX)
__device__ __forceinline__ void bulk_g2s(uint32_t dst, const void* src, uint32_t bytes, uint32_t mbar) {
    asm volatile(
        "cp.async.bulk.shared::cluster.global.mbarrier::complete_tx::bytes [%0], [%1], %2, [%3];"
        :: "r"(dst), "l"(src), "r"(bytes), "r"(mbar) : "memory");
}

__device__ __forceinline__ void ldsm4(uint32_t* r, uint32_t addr) {
    asm volatile("ldmatrix.sync.aligned.m8n8.x4.shared.b16 {%0,%1,%2,%3}, [%4];"
                 : "=r"(r[0]), "=r"(r[1]), "=r"(r[2]), "=r"(r[3]) : "r"(addr));
}

__device__ __forceinline__ void mma16816(float* c, const uint32_t* a, uint32_t b0, uint32_t b1) {
    asm volatile(
        "mma.sync.aligned.m16n8k16.row.col.f32.f16.f16.f32 "
        "{%0,%1,%2,%3}, {%4,%5,%6,%7}, {%8,%9}, {%0,%1,%2,%3};"
        : "+f"(c[0]), "+f"(c[1]), "+f"(c[2]), "+f"(c[3])
        : "r"(a[0]), "r"(a[1]), "r"(a[2]), "r"(a[3]), "r"(b0), "r"(b1));
}

// ====================== pre-convert kernels (write swizzled tiled layout) ======
// out 16B chunk (mt,it,r,c): byte off = ((mt*KITERS+it)*A_BYTES) + r*128 + ((c*16)^((r&7)<<4))
__global__ void conv_a_tiled(const float4* __restrict__ in, char* __restrict__ outb, int total) {
    int t = blockIdx.x * blockDim.x + threadIdx.x;
    if (t >= total) return;                      // total = 4194304
    int c  = t & 7;
    int r  = (t >> 3) & 127;
    int it = (t >> 10) & 63;
    int mt = t >> 16;
    int m = mt * 128 + r;
    int k = it * 64 + c * 8;
    const float4* src = in + ((size_t)m * K_TOTAL + k) / 4;   // 8 floats = 2 x float4
    float4 v0 = src[0], v1 = src[1];
    __half2 h0 = __floats2half2_rn(v0.x, v0.y);
    __half2 h1 = __floats2half2_rn(v0.z, v0.w);
    __half2 h2 = __floats2half2_rn(v1.x, v1.y);
    __half2 h3 = __floats2half2_rn(v1.z, v1.w);
    size_t off = (size_t)(mt * KITERS + it) * A_BYTES + r * 128 + ((c * 16) ^ ((r & 7) << 4));
    uint4 pk;
    pk.x = *(uint32_t*)&h0; pk.y = *(uint32_t*)&h1;
    pk.z = *(uint32_t*)&h2; pk.w = *(uint32_t*)&h3;
    *reinterpret_cast<uint4*>(outb + off) = pk;
}

__global__ void conv_w_tiled(const int4* __restrict__ in, char* __restrict__ outb, int total) {
    int t = blockIdx.x * blockDim.x + threadIdx.x;
    if (t >= total) return;                      // total = 8388608
    int c  = t & 7;
    int r  = (t >> 3) & 255;
    int it = (t >> 11) & 63;
    int nt = t >> 17;
    int n = nt * 256 + r;
    int k = it * 64 + c * 8;
    const int4* src = in + ((size_t)n * K_TOTAL + k) / 4;     // 8 ints = 2 x int4
    int4 w0 = src[0], w1 = src[1];
    __half2 h0 = __floats2half2_rn((float)w0.x, (float)w0.y); // exact: |w|<=127
    __half2 h1 = __floats2half2_rn((float)w0.z, (float)w0.w);
    __half2 h2 = __floats2half2_rn((float)w1.x, (float)w1.y);
    __half2 h3 = __floats2half2_rn((float)w1.z, (float)w1.w);
    size_t off = (size_t)(nt * KITERS + it) * W_BYTES + r * 128 + ((c * 16) ^ ((r & 7) << 4));
    uint4 pk;
    pk.x = *(uint32_t*)&h0; pk.y = *(uint32_t*)&h1;
    pk.z = *(uint32_t*)&h2; pk.w = *(uint32_t*)&h3;
    *reinterpret_cast<uint4*>(outb + off) = pk;
}

// ====================== GEMM kernel (HMMA + bulk-copy pipeline) ======================
__global__ void __launch_bounds__(THREADS, 1) qlinear_gemm(
    const float* __restrict__ scale,
    const float* __restrict__ bias,
    float* __restrict__ out)
{
    extern __shared__ char smem_raw[];
    uint32_t raw = smem_u32(smem_raw);
    uint32_t pad = (1024u - (raw & 1023u)) & 1023u;
    uint32_t sb = raw + pad;
    char* smbase = smem_raw + pad;

    const int tid = threadIdx.x;
    const int wid = tid >> 5;
    const int lid = tid & 31;
    const int warp_m = wid & 3;
    const int warp_n = wid >> 2;

    // ---- rasterization: groups of 8 N-tiles ----
    const int MT = M_TOTAL / TM;             // 64
    const int G = 8;
    const int PER = G * MT;                  // 512
    int bid = blockIdx.x;
    int grp = bid / PER;
    int r = bid % PER;
    int nt = grp * G + (r % G);
    int mt = r / G;
    int m0 = mt * TM;
    int n0 = nt * TN;

    const char* a_tiles = (const char*)g_A + (size_t)mt * KITERS * A_BYTES;
    const char* w_tiles = (const char*)g_W + (size_t)nt * KITERS * W_BYTES;

    // ---- barrier init ----
    if (tid == 0) {
        #pragma unroll
        for (int s = 0; s < STAGES; ++s) {
            MBAR_INIT(sb + OFF_BAR + s * 16, 1u);        // full: expect_tx arrival
            MBAR_INIT(sb + OFF_BAR + s * 16 + 8, 16u);   // empty: 16 warp arrivals
        }
        asm volatile("fence.proxy.async.shared::cta;" ::: "memory");
    }
    // ---- scale/bias -> smem ----
    float* ssm = (float*)(smbase + OFF_SCALE);
    float* bsm = (float*)(smbase + OFF_BIAS);
    if (tid < TN) {
        ssm[tid] = scale[n0 + tid];
        bsm[tid] = bias[n0 + tid];
    }
    __syncthreads();

    // ---- prologue: producer fills stages 0..2 ----
    if (tid == 0) {
        #pragma unroll
        for (int j = 0; j < STAGES - 1; ++j) {
            uint32_t fb = sb + OFF_BAR + j * 16;
            MBAR_EXPECT_TX(fb, (uint32_t)STAGE_BYTES);
            uint32_t stg = sb + j * STAGE_BYTES;
            bulk_g2s(stg,           a_tiles + (size_t)j * A_BYTES, A_BYTES, fb);
            bulk_g2s(stg + A_BYTES, w_tiles + (size_t)j * W_BYTES, W_BYTES, fb);
        }
    }

    // ---- ldmatrix lane address precompute ----
    int lrow = lid & 15;
    int lk16 = (lid >> 4) * 16;
    uint32_t a_rb[2], a_rx[2];
    #pragma unroll
    for (int mtt = 0; mtt < 2; ++mtt) {
        int rowi = warp_m * 32 + mtt * 16 + lrow;
        a_rb[mtt] = rowi * 128;
        a_rx[mtt] = (rowi & 7) << 4;
    }
    uint32_t b_rb[4], b_rx[4];
    #pragma unroll
    for (int nb = 0; nb < 4; ++nb) {
        int rowi = warp_n * 64 + nb * 16 + lrow;
        b_rb[nb] = A_BYTES + rowi * 128;
        b_rx[nb] = (rowi & 7) << 4;
    }

    float acc[2][8][4];
    #pragma unroll
    for (int i = 0; i < 2; ++i)
        #pragma unroll
        for (int j = 0; j < 8; ++j)
            #pragma unroll
            for (int k = 0; k < 4; ++k) acc[i][j][k] = 0.0f;

    // producer cursor (tid 0): next production j = 3; stage 3, phase 1
    int sp = STAGES - 1, pp = 1;

    // ---- mainloop ----
    for (int it = 0; it < KITERS; ++it) {
        // producer: issue k-iter it+3 (3 stages ahead)
        if (tid == 0) {
            int j = it + STAGES - 1;
            if (j < KITERS) {
                uint32_t eb = sb + OFF_BAR + sp * 16 + 8;
                mbar_wait_relaxed(eb, (uint32_t)pp);
                uint32_t fb = sb + OFF_BAR + sp * 16;
                MBAR_EXPECT_TX(fb, (uint32_t)STAGE_BYTES);
                uint32_t stg = sb + sp * STAGE_BYTES;
                bulk_g2s(stg,           a_tiles + (size_t)j * A_BYTES, A_BYTES, fb);
                bulk_g2s(stg + A_BYTES, w_tiles + (size_t)j * W_BYTES, W_BYTES, fb);
                if (++sp == STAGES) { sp = 0; pp ^= 1; }
            }
        }

        // consumer: wait stage full
        int sc = it & (STAGES - 1);
        mbar_wait(sb + OFF_BAR + sc * 16, (uint32_t)((it >> 2) & 1));

        uint32_t st = sb + sc * STAGE_BYTES;
        #pragma unroll
        for (int ks = 0; ks < 4; ++ks) {
            uint32_t kb = ks * 32 + lk16;
            uint32_t a[2][4], b[4][4];
            #pragma unroll
            for (int mtt = 0; mtt < 2; ++mtt)
                ldsm4(a[mtt], st + a_rb[mtt] + (kb ^ a_rx[mtt]));
            #pragma unroll
            for (int nb = 0; nb < 4; ++nb)
                ldsm4(b[nb], st + b_rb[nb] + (kb ^ b_rx[nb]));
            #pragma unroll
            for (int mtt = 0; mtt < 2; ++mtt) {
                #pragma unroll
                for (int nb = 0; nb < 4; ++nb) {
                    mma16816(acc[mtt][2 * nb],     a[mtt], b[nb][0], b[nb][2]);
                    mma16816(acc[mtt][2 * nb + 1], a[mtt], b[nb][1], b[nb][3]);
                }
            }
        }

        // release stage (one arrive per warp)
        if (lid == 0) MBAR_ARRIVE(sb + OFF_BAR + sc * 16 + 8);
    }

    // ---- epilogue: scale * acc + bias, fp32 stores ----
    int qrow = lid >> 2;
    int qcol = (lid & 3) * 2;
    #pragma unroll
    for (int mtt = 0; mtt < 2; ++mtt) {
        int r0 = m0 + warp_m * 32 + mtt * 16 + qrow;
        int r1 = r0 + 8;
        #pragma unroll
        for (int nb8 = 0; nb8 < 8; ++nb8) {
            int nl = warp_n * 64 + nb8 * 8 + qcol;
            float s0 = ssm[nl], s1 = ssm[nl + 1];
            float b0 = bsm[nl], b1 = bsm[nl + 1];
            float2 v0, v1;
            v0.x = acc[mtt][nb8][0] * s0 + b0;
            v0.y = acc[mtt][nb8][1] * s1 + b1;
            v1.x = acc[mtt][nb8][2] * s0 + b0;
            v1.y = acc[mtt][nb8][3] * s1 + b1;
            *reinterpret_cast<float2*>(out + (size_t)r0 * N_TOTAL + n0 + nl) = v0;
            *reinterpret_cast<float2*>(out + (size_t)r1 * N_TOTAL + n0 + nl) = v1;
        }
    }
}

// ====================== host launch ======================
extern "C" void kernel_launch(void* const* d_in, const int* in_sizes, int n_in,
                              void* d_out, int out_size) {
    const float* inp = (const float*)d_in[0];   // [4,2048,4096] fp32
    const int*   qw  = (const int*)d_in[1];     // [16384,4096] int32
    const float* sw  = (const float*)d_in[2];   // [16384]
    const float* bs  = (const float*)d_in[3];   // [16384]
    float* out = (float*)d_out;

    void *pA = nullptr, *pW = nullptr;
    cudaGetSymbolAddress(&pA, g_A);
    cudaGetSymbolAddress(&pW, g_W);

    {
        int total = (M_TOTAL * K_TOTAL) / 8;    // 4194304 chunks of 16B out
        conv_a_tiled<<<total / 256, 256>>>((const float4*)inp, (char*)pA, total);
    }
    {
        int total = (N_TOTAL * K_TOTAL) / 8;    // 8388608
        conv_w_tiled<<<total / 256, 256>>>((const int4*)qw, (char*)pW, total);
    }

    cudaFuncSetAttribute(qlinear_gemm, cudaFuncAttributeMaxDynamicSharedMemorySize, SMEM_DYN);
    int grid = (M_TOTAL / TM) * (N_TOTAL / TN);  // 4096
    qlinear_gemm<<<grid, THREADS, SMEM_DYN>>>(sw, bs, out);
}

// round 4
// speedup vs baseline: 1.1720x; 1.0552x over previous
#include <cuda_runtime.h>
#include <cuda_fp16.h>
#include <cstdint>

// ====================== problem constants ======================
#define M_TOTAL 8192
#define N_TOTAL 16384
#define K_TOTAL 4096

#define TM 128
#define TN 256
#define TK 64                    // fp16 elems per K-chunk (128 B per row)
#define STAGES 4
#define KITERS (K_TOTAL / TK)    // 64
#define NTILES ((M_TOTAL / TM) * (N_TOTAL / TN))   // 4096
#define THREADS 544              // 16 consumer warps + 1 producer warp

#define A_BYTES (TM * TK * 2)           // 16384
#define W_BYTES (TN * TK * 2)           // 32768
#define STAGE_BYTES (A_BYTES + W_BYTES) // 49152

#define OFF_BAR   (STAGES * STAGE_BYTES)   // 196608: [full(8B), empty(8B)] x STAGES
#define SMEM_NEED (OFF_BAR + STAGES * 16)
#define SMEM_DYN  (SMEM_NEED + 1024)

// ====================== device scratch (pre-swizzled tiled layouts) ==================
// A: tiles [mt][kit], TM rows x 128B (SW128-swizzled), 16KB each, contiguous
// W: tiles [nt][kit], TN rows x 128B (SW128-swizzled), 32KB each, contiguous
__device__ __align__(128) __half g_A[(size_t)M_TOTAL * K_TOTAL];
__device__ __align__(128) __half g_W[(size_t)N_TOTAL * K_TOTAL];

// ====================== PTX helpers (generic PTX only) ======================
__device__ __forceinline__ uint32_t smem_u32(const void* p) {
    uint32_t a;
    asm("{ .reg .u64 t; cvta.to.shared.u64 t, %1; cvt.u32.u64 %0, t; }" : "=r"(a) : "l"(p));
    return a;
}

#define MBAR_INIT(addr, cnt) \
    asm volatile("mbarrier.init.shared.b64 [%0], %1;" :: "r"(addr), "r"(cnt) : "memory")

#define MBAR_EXPECT_TX(addr, bytes) \
    asm volatile("mbarrier.arrive.expect_tx.shared.b64 _, [%0], %1;" :: "r"(addr), "r"(bytes) : "memory")

#define MBAR_ARRIVE(addr) \
    asm volatile("mbarrier.arrive.shared.b64 _, [%0];" :: "r"(addr) : "memory")

__device__ __forceinline__ void mbar_wait(uint32_t mbar, uint32_t parity) {
    asm volatile(
        "{\n\t.reg .pred P;\n\t"
        "WAIT_%=:\n\t"
        "mbarrier.try_wait.parity.acquire.cta.shared::cta.b64 P, [%0], %1, 0x989680;\n\t"
        "@P bra.uni DONE_%=;\n\t"
        "bra.uni WAIT_%=;\n\t"
        "DONE_%=:\n\t}"
        :: "r"(mbar), "r"(parity) : "memory");
}

__device__ __forceinline__ void mbar_wait_relaxed(uint32_t mbar, uint32_t parity) {
    asm volatile(
        "{\n\t.reg .pred P;\n\t"
        "WAIT_%=:\n\t"
        "mbarrier.try_wait.parity.relaxed.cta.shared::cta.b64 P, [%0], %1, 0x989680;\n\t"
        "@P bra.uni DONE_%=;\n\t"
        "bra.uni WAIT_%=;\n\t"
        "DONE_%=:\n\t}"
        :: "r"(mbar), "r"(parity) : "memory");
}

__device__ __forceinline__ void bulk_g2s(uint32_t dst, const void* src, uint32_t bytes, uint32_t mbar) {
    asm volatile(
        "cp.async.bulk.shared::cluster.global.mbarrier::complete_tx::bytes [%0], [%1], %2, [%3];"
        :: "r"(dst), "l"(src), "r"(bytes), "r"(mbar) : "memory");
}

__device__ __forceinline__ void ldsm4(uint32_t* r, uint32_t addr) {
    asm volatile("ldmatrix.sync.aligned.m8n8.x4.shared.b16 {%0,%1,%2,%3}, [%4];"
                 : "=r"(r[0]), "=r"(r[1]), "=r"(r[2]), "=r"(r[3]) : "r"(addr));
}

__device__ __forceinline__ void mma16816(float* c, const uint32_t* a, uint32_t b0, uint32_t b1) {
    asm volatile(
        "mma.sync.aligned.m16n8k16.row.col.f32.f16.f16.f32 "
        "{%0,%1,%2,%3}, {%4,%5,%6,%7}, {%8,%9}, {%0,%1,%2,%3};"
        : "+f"(c[0]), "+f"(c[1]), "+f"(c[2]), "+f"(c[3])
        : "r"(a[0]), "r"(a[1]), "r"(a[2]), "r"(a[3]), "r"(b0), "r"(b1));
}

// ====================== pre-convert kernels (write swizzled tiled layout) ======
__global__ void conv_a_tiled(const float4* __restrict__ in, char* __restrict__ outb, int total) {
    int t = blockIdx.x * blockDim.x + threadIdx.x;
    if (t >= total) return;
    int c  = t & 7;
    int r  = (t >> 3) & 127;
    int it = (t >> 10) & 63;
    int mt = t >> 16;
    int m = mt * 128 + r;
    int k = it * 64 + c * 8;
    const float4* src = in + ((size_t)m * K_TOTAL + k) / 4;
    float4 v0 = src[0], v1 = src[1];
    __half2 h0 = __floats2half2_rn(v0.x, v0.y);
    __half2 h1 = __floats2half2_rn(v0.z, v0.w);
    __half2 h2 = __floats2half2_rn(v1.x, v1.y);
    __half2 h3 = __floats2half2_rn(v1.z, v1.w);
    size_t off = (size_t)(mt * KITERS + it) * A_BYTES + r * 128 + ((c * 16) ^ ((r & 7) << 4));
    uint4 pk;
    pk.x = *(uint32_t*)&h0; pk.y = *(uint32_t*)&h1;
    pk.z = *(uint32_t*)&h2; pk.w = *(uint32_t*)&h3;
    *reinterpret_cast<uint4*>(outb + off) = pk;
}

__global__ void conv_w_tiled(const int4* __restrict__ in, char* __restrict__ outb, int total) {
    int t = blockIdx.x * blockDim.x + threadIdx.x;
    if (t >= total) return;
    int c  = t & 7;
    int r  = (t >> 3) & 255;
    int it = (t >> 11) & 63;
    int nt = t >> 17;
    int n = nt * 256 + r;
    int k = it * 64 + c * 8;
    const int4* src = in + ((size_t)n * K_TOTAL + k) / 4;
    int4 w0 = src[0], w1 = src[1];
    __half2 h0 = __floats2half2_rn((float)w0.x, (float)w0.y);
    __half2 h1 = __floats2half2_rn((float)w0.z, (float)w0.w);
    __half2 h2 = __floats2half2_rn((float)w1.x, (float)w1.y);
    __half2 h3 = __floats2half2_rn((float)w1.z, (float)w1.w);
    size_t off = (size_t)(nt * KITERS + it) * W_BYTES + r * 128 + ((c * 16) ^ ((r & 7) << 4));
    uint4 pk;
    pk.x = *(uint32_t*)&h0; pk.y = *(uint32_t*)&h1;
    pk.z = *(uint32_t*)&h2; pk.w = *(uint32_t*)&h3;
    *reinterpret_cast<uint4*>(outb + off) = pk;
}

// ====================== tile mapping (shared by producer/consumer) ============
__device__ __forceinline__ void tile_mn(int t, int& m0, int& n0) {
    const int G = 8;
    const int MT = M_TOTAL / TM;          // 64
    const int PER = G * MT;               // 512
    int grp = t / PER;
    int r = t % PER;
    int nt = grp * G + (r % G);
    int mt = r / G;
    m0 = mt * TM;
    n0 = nt * TN;
}

// ====================== persistent warp-specialized GEMM ======================
__global__ void __launch_bounds__(THREADS, 1) qlinear_gemm(
    const float* __restrict__ scale,
    const float* __restrict__ bias,
    float* __restrict__ out)
{
    extern __shared__ char smem_raw[];
    uint32_t raw = smem_u32(smem_raw);
    uint32_t pad = (1024u - (raw & 1023u)) & 1023u;
    uint32_t sb = raw + pad;

    const int tid = threadIdx.x;
    const int wid = tid >> 5;
    const int lid = tid & 31;

    if (tid == 0) {
        #pragma unroll
        for (int s = 0; s < STAGES; ++s) {
            MBAR_INIT(sb + OFF_BAR + s * 16, 1u);        // full: tx-count arrival
            MBAR_INIT(sb + OFF_BAR + s * 16 + 8, 16u);   // empty: 16 consumer warps
        }
        asm volatile("fence.proxy.async.shared::cta;" ::: "memory");
    }
    __syncthreads();

    const int grid = gridDim.x;
    const int bid = blockIdx.x;

    // =================== producer warp (warp 16) ===================
    if (wid == 16) {
        if (lid == 0) {
            uint32_t g = 0;   // global k-iteration index for this CTA's tile stream
            for (int t = bid; t < NTILES; t += grid) {
                int m0, n0;
                tile_mn(t, m0, n0);
                const char* a_tiles = (const char*)g_A + ((size_t)(m0 / TM) * KITERS) * A_BYTES;
                const char* w_tiles = (const char*)g_W + ((size_t)(n0 / TN) * KITERS) * W_BYTES;
                for (int it = 0; it < KITERS; ++it, ++g) {
                    uint32_t s = g & (STAGES - 1);
                    uint32_t fb = sb + OFF_BAR + s * 16;
                    mbar_wait_relaxed(fb + 8, ((g >> 2) & 1u) ^ 1u);
                    MBAR_EXPECT_TX(fb, (uint32_t)STAGE_BYTES);
                    uint32_t stg = sb + s * STAGE_BYTES;
                    bulk_g2s(stg,           a_tiles + (size_t)it * A_BYTES, A_BYTES, fb);
                    bulk_g2s(stg + A_BYTES, w_tiles + (size_t)it * W_BYTES, W_BYTES, fb);
                }
            }
        }
        return;
    }

    // =================== consumer warps (0..15) ===================
    const int warp_m = wid & 3;
    const int warp_n = wid >> 2;

    // ldmatrix lane address precompute (stage-relative)
    int lrow = lid & 15;
    int lk16 = (lid >> 4) * 16;
    uint32_t a_rb[2], a_rx[2];
    #pragma unroll
    for (int mtt = 0; mtt < 2; ++mtt) {
        int rowi = warp_m * 32 + mtt * 16 + lrow;
        a_rb[mtt] = rowi * 128;
        a_rx[mtt] = (rowi & 7) << 4;
    }
    uint32_t b_rb[4], b_rx[4];
    #pragma unroll
    for (int nb = 0; nb < 4; ++nb) {
        int rowi = warp_n * 64 + nb * 16 + lrow;
        b_rb[nb] = A_BYTES + rowi * 128;
        b_rx[nb] = (rowi & 7) << 4;
    }

    const int qrow = lid >> 2;
    const int qcol = (lid & 3) * 2;

    uint32_t g = 0;
    for (int t = bid; t < NTILES; t += grid) {
        int m0, n0;
        tile_mn(t, m0, n0);

        float acc[2][8][4];
        #pragma unroll
        for (int i = 0; i < 2; ++i)
            #pragma unroll
            for (int j = 0; j < 8; ++j)
                #pragma unroll
                for (int k = 0; k < 4; ++k) acc[i][j][k] = 0.0f;

        for (int it = 0; it < KITERS; ++it, ++g) {
            uint32_t s = g & (STAGES - 1);
            mbar_wait(sb + OFF_BAR + s * 16, (g >> 2) & 1u);

            uint32_t st = sb + s * STAGE_BYTES;
            #pragma unroll
            for (int ks = 0; ks < 4; ++ks) {
                uint32_t kb = ks * 32 + lk16;
                uint32_t a[2][4], b[4][4];
                #pragma unroll
                for (int mtt = 0; mtt < 2; ++mtt)
                    ldsm4(a[mtt], st + a_rb[mtt] + (kb ^ a_rx[mtt]));
                #pragma unroll
                for (int nb = 0; nb < 4; ++nb)
                    ldsm4(b[nb], st + b_rb[nb] + (kb ^ b_rx[nb]));
                #pragma unroll
                for (int mtt = 0; mtt < 2; ++mtt) {
                    #pragma unroll
                    for (int nb = 0; nb < 4; ++nb) {
                        mma16816(acc[mtt][2 * nb],     a[mtt], b[nb][0], b[nb][2]);
                        mma16816(acc[mtt][2 * nb + 1], a[mtt], b[nb][1], b[nb][3]);
                    }
                }
            }
            if (lid == 0) MBAR_ARRIVE(sb + OFF_BAR + s * 16 + 8);
        }

        // epilogue: scale * acc + bias (scale/bias via L2-cached float2 loads)
        #pragma unroll
        for (int nb8 = 0; nb8 < 8; ++nb8) {
            int nl = warp_n * 64 + nb8 * 8 + qcol;
            float2 sv = __ldg(reinterpret_cast<const float2*>(scale + n0 + nl));
            float2 bv = __ldg(reinterpret_cast<const float2*>(bias + n0 + nl));
            #pragma unroll
            for (int mtt = 0; mtt < 2; ++mtt) {
                int r0 = m0 + warp_m * 32 + mtt * 16 + qrow;
                float2 v0, v1;
                v0.x = acc[mtt][nb8][0] * sv.x + bv.x;
                v0.y = acc[mtt][nb8][1] * sv.y + bv.y;
                v1.x = acc[mtt][nb8][2] * sv.x + bv.x;
                v1.y = acc[mtt][nb8][3] * sv.y + bv.y;
                *reinterpret_cast<float2*>(out + (size_t)r0 * N_TOTAL + n0 + nl) = v0;
                *reinterpret_cast<float2*>(out + (size_t)(r0 + 8) * N_TOTAL + n0 + nl) = v1;
            }
        }
    }
}

// ====================== host launch ======================
extern "C" void kernel_launch(void* const* d_in, const int* in_sizes, int n_in,
                              void* d_out, int out_size) {
    const float* inp = (const float*)d_in[0];   // [4,2048,4096] fp32
    const int*   qw  = (const int*)d_in[1];     // [16384,4096] int32
    const float* sw  = (const float*)d_in[2];   // [16384]
    const float* bs  = (const float*)d_in[3];   // [16384]
    float* out = (float*)d_out;

    void *pA = nullptr, *pW = nullptr;
    cudaGetSymbolAddress(&pA, g_A);
    cudaGetSymbolAddress(&pW, g_W);

    {
        int total = (M_TOTAL * K_TOTAL) / 8;
        conv_a_tiled<<<total / 256, 256>>>((const float4*)inp, (char*)pA, total);
    }
    {
        int total = (N_TOTAL * K_TOTAL) / 8;
        conv_w_tiled<<<total / 256, 256>>>((const int4*)qw, (char*)pW, total);
    }

    static int nsm = 0;
    if (nsm == 0) {
        cudaDeviceGetAttribute(&nsm, cudaDevAttrMultiProcessorCount, 0);
        if (nsm <= 0) nsm = 148;
    }

    cudaFuncSetAttribute(qlinear_gemm, cudaFuncAttributeMaxDynamicSharedMemorySize, SMEM_DYN);
    qlinear_gemm<<<nsm, THREADS, SMEM_DYN>>>(sw, bs, out);
}